// round 2
// baseline (speedup 1.0000x reference)
#include <cuda_runtime.h>
#include <math.h>

// MaskAttention: B=4, L=2048, H=8, E=D=64.
// Sparse attention exploiting the deterministic LocalLogSymmetryMask:
// each row attends <= ~47 columns (local +-5 window + log-spaced 1.5^k offsets).

#define BB 4
#define LL 2048
#define HH 8
#define EE 64
#define DD 64
#define MAXNNZ 64

// Scratch: per-row allowed-column lists (rebuilt every launch; deterministic).
__device__ int g_cols[LL][MAXNNZ];
__device__ int g_nnz[LL];

// ---------------------------------------------------------------------------
// Kernel 1: analytically rebuild the allowed-column list for each row.
// Exact port of _build_local_log_symmetry_mask (allowed = mask==False):
//   left:  if i-lws+1 < 0: [0, i)            (no log terms)
//          else:           [i-lws+1, i] + { i-lws+1 - int(1.5^k) >= 0 }
//   right: if i+lws-1 >= L: [i, L)           (no log terms)
//          else:           [i, i+lws-1] + { i+lws-1 + int(1.5^k) < L }
// The union of the window parts is always the contiguous range
// [max(i-lws+1,0), min(i+lws-1,L-1)] (covers both edge branches).
// int(1.5^k) is exact in double (3^k/2^k); k=0 and k=1 both give offset 1,
// so start at k=1 to avoid the duplicate. Offsets are monotone after that,
// so the "break" semantics match Python's.
// ---------------------------------------------------------------------------
__global__ void build_cols_kernel(int lws) {
    int i = blockIdx.x * blockDim.x + threadIdx.x;
    if (i >= LL) return;

    int cnt = 0;
    int wlo = i - lws + 1;
    int whi = i + lws - 1;

    // left log terms (only when the left window fits)
    if (wlo >= 0) {
        double off = 1.5;  // k = 1
        #pragma unroll 1
        for (int k = 1; k < 200; k++) {
            int ni = wlo - (int)off;
            if (ni < 0) break;
            if (cnt < MAXNNZ) g_cols[i][cnt++] = ni;
            off *= 1.5;
        }
    }
    // contiguous window (covers row[:i] / row[i:] edge branches too)
    int lo = wlo < 0 ? 0 : wlo;
    int hi = whi >= LL ? LL - 1 : whi;
    for (int j = lo; j <= hi; j++)
        if (cnt < MAXNNZ) g_cols[i][cnt++] = j;
    // right log terms (only when the right window fits)
    if (whi < LL) {
        double off = 1.5;  // k = 1
        #pragma unroll 1
        for (int k = 1; k < 200; k++) {
            int ni = whi + (int)off;
            if (ni >= LL) break;
            if (cnt < MAXNNZ) g_cols[i][cnt++] = ni;
            off *= 1.5;
        }
    }
    g_nnz[i] = cnt;
}

// ---------------------------------------------------------------------------
// Kernel 2: sparse attention. Grid (L, B); block (32, 8) = 1 warp per head.
// Phase A: each lane computes scores for columns j=lane and j=lane+32
//          (float4 dot vs smem-staged q), warp-shfl softmax, probs -> smem.
// Phase B: each lane owns output dims {lane, lane+32}; coalesced 256B V rows.
// ---------------------------------------------------------------------------
__global__ __launch_bounds__(256) void attn_kernel(
    const float* __restrict__ q,
    const float* __restrict__ k,
    const float* __restrict__ v,
    float* __restrict__ out)
{
    const int i = blockIdx.x;      // query row
    const int b = blockIdx.y;      // batch
    const int h = threadIdx.y;     // head (warp id)
    const int lane = threadIdx.x;
    const int tid = h * 32 + lane;

    __shared__ float qs[HH][EE];
    __shared__ float ps[HH][MAXNNZ];
    __shared__ int   cols_s[MAXNNZ];

    // stage q[b,i,:,:] (512 floats, contiguous) + column list
    const float* qrow = q + ((size_t)(b * LL + i) * HH) * EE;
    {
        float* qflat = &qs[0][0];
        #pragma unroll
        for (int t = tid; t < HH * EE; t += 256) qflat[t] = qrow[t];
    }
    const int nnz = g_nnz[i];
    if (tid < MAXNNZ) cols_s[tid] = (tid < nnz) ? g_cols[i][tid] : 0;
    __syncthreads();

    const float scale = 0.125f;  // 1/sqrt(64)

    // ---- Phase A: scores + softmax (per-warp, per-head) ----
    const int j0 = lane, j1 = lane + 32;
    float s0 = -INFINITY, s1 = -INFINITY;
    const float4* qp = (const float4*)qs[h];

    if (j0 < nnz) {
        const float4* kp = (const float4*)(k + ((size_t)(b * LL + cols_s[j0]) * HH + h) * EE);
        float acc = 0.f;
        #pragma unroll
        for (int t = 0; t < EE / 4; t++) {
            float4 kv = kp[t], qv = qp[t];
            acc = fmaf(kv.x, qv.x, acc); acc = fmaf(kv.y, qv.y, acc);
            acc = fmaf(kv.z, qv.z, acc); acc = fmaf(kv.w, qv.w, acc);
        }
        s0 = acc * scale;
    }
    if (j1 < nnz) {
        const float4* kp = (const float4*)(k + ((size_t)(b * LL + cols_s[j1]) * HH + h) * EE);
        float acc = 0.f;
        #pragma unroll
        for (int t = 0; t < EE / 4; t++) {
            float4 kv = kp[t], qv = qp[t];
            acc = fmaf(kv.x, qv.x, acc); acc = fmaf(kv.y, qv.y, acc);
            acc = fmaf(kv.z, qv.z, acc); acc = fmaf(kv.w, qv.w, acc);
        }
        s1 = acc * scale;
    }

    float m = fmaxf(s0, s1);
    #pragma unroll
    for (int o = 16; o > 0; o >>= 1) m = fmaxf(m, __shfl_xor_sync(0xFFFFFFFFu, m, o));
    float e0 = (j0 < nnz) ? __expf(s0 - m) : 0.f;
    float e1 = (j1 < nnz) ? __expf(s1 - m) : 0.f;
    float sum = e0 + e1;
    #pragma unroll
    for (int o = 16; o > 0; o >>= 1) sum += __shfl_xor_sync(0xFFFFFFFFu, sum, o);
    const float inv = 1.f / sum;
    if (j0 < nnz) ps[h][j0] = e0 * inv;
    if (j1 < nnz) ps[h][j1] = e1 * inv;
    __syncwarp();

    // ---- Phase B: weighted sum of values; lane owns dims {lane, lane+32} ----
    float a0 = 0.f, a1 = 0.f;
    #pragma unroll 4
    for (int j = 0; j < nnz; j++) {
        const float pj = ps[h][j];
        const float* vp = v + ((size_t)(b * LL + cols_s[j]) * HH + h) * DD;
        a0 = fmaf(pj, vp[lane], a0);
        a1 = fmaf(pj, vp[lane + 32], a1);
    }
    float* op = out + ((size_t)(b * LL + i) * HH + h) * DD;
    op[lane] = a0;
    op[lane + 32] = a1;
}

// ---------------------------------------------------------------------------
extern "C" void kernel_launch(void* const* d_in, const int* in_sizes, int n_in,
                              void* d_out, int out_size) {
    const float* q = (const float*)d_in[0];
    const float* k = (const float*)d_in[1];
    const float* v = (const float*)d_in[2];
    // d_in[3] = mask, unused: reconstructed analytically (deterministic for L).
    float* out = (float*)d_out;

    const int lws = (int)ceil(log2((double)LL) / 2.0);  // = 6 for L=2048

    build_cols_kernel<<<(LL + 255) / 256, 256>>>(lws);

    dim3 grid(LL, BB);
    dim3 block(32, HH);
    attn_kernel<<<grid, block>>>(q, k, v, out);
}

// round 7
// speedup vs baseline: 1.1437x; 1.1437x over previous
#include <cuda_runtime.h>
#include <math.h>

// MaskAttention: B=4, L=2048, H=8, E=D=64.
// Sparse attention on the deterministic LocalLogSymmetryMask:
// each row attends <= 46 columns (local +-5 window + log-spaced 1.5^k offsets).
//
// R6: R2's transpose-through-smem Phase A, but ALL-STATIC shared memory
// (30 KB/block < 48 KB default limit -- R2 failed launch on 52.5 KB total).
// Columns processed in two halves of <=23 so the per-head tile is
// 32 e-rows x pitch 25 (odd => conflict-free stores and reads).

#define BB 4
#define LL 2048
#define HH 8
#define EE 64
#define DD 64
#define MAXNNZ 64    // storage bound; actual nnz <= 46
#define CHALF 23     // columns per half
#define TPITCH 25    // odd -> conflict-free
#define KTILE (32 * TPITCH)

// Scratch: per-row allowed-column lists (rebuilt every launch; deterministic).
__device__ int g_cols[LL][MAXNNZ];
__device__ int g_nnz[LL];

// ---------------------------------------------------------------------------
// Kernel 1: analytically rebuild the allowed-column list for each row.
// Exact port of _build_local_log_symmetry_mask (allowed = mask==False).
// int(1.5^k) is exact in double; k=0 and k=1 both give 1, start at k=1.
// ---------------------------------------------------------------------------
__global__ void build_cols_kernel(int lws) {
    int i = blockIdx.x * blockDim.x + threadIdx.x;
    if (i >= LL) return;

    int cnt = 0;
    int wlo = i - lws + 1;
    int whi = i + lws - 1;

    if (wlo >= 0) {
        double off = 1.5;  // k = 1
        #pragma unroll 1
        for (int k = 1; k < 200; k++) {
            int ni = wlo - (int)off;
            if (ni < 0) break;
            if (cnt < MAXNNZ) g_cols[i][cnt++] = ni;
            off *= 1.5;
        }
    }
    int lo = wlo < 0 ? 0 : wlo;
    int hi = whi >= LL ? LL - 1 : whi;
    for (int j = lo; j <= hi; j++)
        if (cnt < MAXNNZ) g_cols[i][cnt++] = j;
    if (whi < LL) {
        double off = 1.5;  // k = 1
        #pragma unroll 1
        for (int k = 1; k < 200; k++) {
            int ni = whi + (int)off;
            if (ni >= LL) break;
            if (cnt < MAXNNZ) g_cols[i][cnt++] = ni;
            off *= 1.5;
        }
    }
    g_nnz[i] = cnt;
}

// ---------------------------------------------------------------------------
// Kernel 2: sparse attention. Grid (L, B); block (32, 8) = 1 warp per head.
// Phase A (per warp): for each column-half c (<=23 cols) and e-half p (32):
//   stage: lane loads k[b,col,h,32p+lane] (coalesced 128B) and stores
//          q[32p+lane]*k at ks[lane*25 + jj]  (conflict-free)
//   score: lane accumulates column (23c + lane) via ks[t*25 + lane]
//          (consecutive lanes -> conflict-free; lanes >= 23 masked later)
// Softmax via warp shfl; probs -> smem.
// Phase B: lane owns dims {2l, 2l+1}; float2 V loads (coalesced 256B rows).
// ---------------------------------------------------------------------------
__global__ __launch_bounds__(256) void attn_kernel(
    const float* __restrict__ q,
    const float* __restrict__ k,
    const float* __restrict__ v,
    float* __restrict__ out)
{
    const int i = blockIdx.x;      // query row
    const int b = blockIdx.y;      // batch
    const int h = threadIdx.y;     // head (warp id)
    const int lane = threadIdx.x;
    const int tid = h * 32 + lane;

    __shared__ float ksd[HH][KTILE];   // 25600 B
    __shared__ float qs[HH][EE];       //  2048 B
    __shared__ float ps[HH][MAXNNZ];   //  2048 B
    __shared__ int   cbase[MAXNNZ];    //   256 B  (head-agnostic element base)

    float* ksw = ksd[h];

    // stage q[b,i,:,:] (512 floats, contiguous) + column element-offsets
    const float* qrow = q + ((size_t)(b * LL + i) * HH) * EE;
    {
        float* qflat = &qs[0][0];
        #pragma unroll
        for (int t = tid; t < HH * EE; t += 256) qflat[t] = qrow[t];
    }
    const int nnz = g_nnz[i];
    if (tid < MAXNNZ)
        cbase[tid] = (tid < nnz) ? (b * LL + g_cols[i][tid]) * (HH * EE) : 0;
    __syncthreads();

    const float scale = 0.125f;  // 1/sqrt(64)
    const float* kh = k + h * EE;

    // ---- Phase A: transposed coalesced gather + dot, two column halves ----
    float s01[2];

    #pragma unroll
    for (int c = 0; c < 2; c++) {
        const int base = c * CHALF;
        int ncol = nnz - base;
        if (ncol > CHALF) ncol = CHALF;

        float ae = 0.f, ao = 0.f;   // two chains to shorten dependencies
        if (ncol > 0) {
            #pragma unroll
            for (int p = 0; p < 2; p++) {
                const int eb = 32 * p;
                const float qv = qs[h][eb + lane];

                #pragma unroll 4
                for (int jj = 0; jj < ncol; jj++) {
                    float kv = kh[cbase[base + jj] + eb + lane]; // coalesced
                    ksw[lane * TPITCH + jj] = kv * qv;           // no conflicts
                }
                __syncwarp();

                #pragma unroll
                for (int t = 0; t < 32; t += 2) {
                    ae += ksw[t * TPITCH + lane];
                    ao += ksw[(t + 1) * TPITCH + lane];
                }
                __syncwarp();
            }
        }
        s01[c] = (lane < ncol) ? (ae + ao) * scale : -INFINITY;
    }

    const int j0 = lane, j1 = CHALF + lane;
    float s0 = s01[0], s1 = s01[1];

    // ---- softmax (warp shfl) ----
    float m = fmaxf(s0, s1);
    #pragma unroll
    for (int o = 16; o > 0; o >>= 1) m = fmaxf(m, __shfl_xor_sync(0xFFFFFFFFu, m, o));
    float e0 = (s0 == -INFINITY) ? 0.f : __expf(s0 - m);
    float e1 = (s1 == -INFINITY) ? 0.f : __expf(s1 - m);
    float sum = e0 + e1;
    #pragma unroll
    for (int o = 16; o > 0; o >>= 1) sum += __shfl_xor_sync(0xFFFFFFFFu, sum, o);
    const float inv = 1.f / sum;
    if (j0 < nnz && lane < CHALF) ps[h][j0] = e0 * inv;
    if (j1 < nnz && lane < CHALF) ps[h][j1] = e1 * inv;
    __syncwarp();

    // ---- Phase B: weighted V sum; lane owns dims {2l, 2l+1} ----
    float b0 = 0.f, b1 = 0.f;
    const float* vh = v + h * DD;
    #pragma unroll 4
    for (int j = 0; j < nnz; j++) {
        const float pj = ps[h][j];
        const float2 vv = *(const float2*)(vh + cbase[j] + 2 * lane);
        b0 = fmaf(pj, vv.x, b0);
        b1 = fmaf(pj, vv.y, b1);
    }
    float2* op = (float2*)(out + ((size_t)(b * LL + i) * HH + h) * DD) + lane;
    *op = make_float2(b0, b1);
}

// ---------------------------------------------------------------------------
extern "C" void kernel_launch(void* const* d_in, const int* in_sizes, int n_in,
                              void* d_out, int out_size) {
    const float* q = (const float*)d_in[0];
    const float* k = (const float*)d_in[1];
    const float* v = (const float*)d_in[2];
    // d_in[3] = mask, unused: reconstructed analytically (deterministic for L).
    float* out = (float*)d_out;

    const int lws = (int)ceil(log2((double)LL) / 2.0);  // = 6 for L=2048

    build_cols_kernel<<<(LL + 255) / 256, 256>>>(lws);

    dim3 grid(LL, BB);
    dim3 block(32, HH);
    attn_kernel<<<grid, block>>>(q, k, v, out);
}

// round 9
// speedup vs baseline: 2.0116x; 1.7588x over previous
#include <cuda_runtime.h>
#include <math.h>

// MaskAttention: B=4, L=2048, H=8, E=D=64.
// Sparse attention on the deterministic LocalLogSymmetryMask:
// each row attends <= 46 columns (local +-5 window + log-spaced 1.5^k offsets).
//
// R7: kill the smem transpose (R6 became issue-bound, alu=39%).
// Direct vectorized dots: 16 lanes x float4 = one 256B K/V row, so each
// warp instruction covers TWO columns (lanes 0-15 -> col 2jp, 16-31 -> 2jp+1).
// Phase A: LDG.128 + 4 FMA + 4 shfl per pair. Phase B: LDG.128 + 4 FMA per
// pair, final shfl-xor-16 combine. Fixed 23-pair unrolled loops with
// zero-padded cbase/ps arrays -> static LDS offsets, minimal ALU.

#define BB 4
#define LL 2048
#define HH 8
#define EE 64
#define DD 64
#define MAXNNZ 64   // storage bound; actual nnz <= 46
#define NPAIR 23    // ceil(46/2) column pairs
#define CPAD 48     // padded column-list length (>= 2*NPAIR)

// Scratch: per-row allowed-column lists (rebuilt every launch; deterministic).
__device__ int g_cols[LL][MAXNNZ];
__device__ int g_nnz[LL];

// ---------------------------------------------------------------------------
// Kernel 1: analytically rebuild the allowed-column list for each row.
// Exact port of _build_local_log_symmetry_mask (allowed = mask==False).
// int(1.5^k) is exact in double; k=0 and k=1 both give 1, start at k=1.
// ---------------------------------------------------------------------------
__global__ void build_cols_kernel(int lws) {
    int i = blockIdx.x * blockDim.x + threadIdx.x;
    if (i >= LL) return;

    int cnt = 0;
    int wlo = i - lws + 1;
    int whi = i + lws - 1;

    if (wlo >= 0) {
        double off = 1.5;  // k = 1
        #pragma unroll 1
        for (int k = 1; k < 200; k++) {
            int ni = wlo - (int)off;
            if (ni < 0) break;
            if (cnt < MAXNNZ) g_cols[i][cnt++] = ni;
            off *= 1.5;
        }
    }
    int lo = wlo < 0 ? 0 : wlo;
    int hi = whi >= LL ? LL - 1 : whi;
    for (int j = lo; j <= hi; j++)
        if (cnt < MAXNNZ) g_cols[i][cnt++] = j;
    if (whi < LL) {
        double off = 1.5;  // k = 1
        #pragma unroll 1
        for (int k = 1; k < 200; k++) {
            int ni = whi + (int)off;
            if (ni >= LL) break;
            if (cnt < MAXNNZ) g_cols[i][cnt++] = ni;
            off *= 1.5;
        }
    }
    g_nnz[i] = cnt;
}

// ---------------------------------------------------------------------------
// Kernel 2: sparse attention. Grid (L, B); block (32, 8) = 1 warp per head.
// ---------------------------------------------------------------------------
__global__ __launch_bounds__(256) void attn_kernel(
    const float* __restrict__ q,
    const float* __restrict__ k,
    const float* __restrict__ v,
    float* __restrict__ out)
{
    const int i = blockIdx.x;      // query row
    const int b = blockIdx.y;      // batch
    const int h = threadIdx.y;     // head (warp id)
    const int lane = threadIdx.x;
    const int tid = h * 32 + lane;
    const int half = lane >> 4;         // which column of the pair
    const int el = (lane & 15) * 4;     // this lane's e/d fragment offset

    __shared__ float ssc[HH][CPAD];     // raw scores
    __shared__ float ps[HH][CPAD];      // probabilities (0-padded)
    __shared__ int   cbase[CPAD];       // (b*LL+col)*H*E element base, 0-padded

    const int nnz = g_nnz[i];
    if (tid < CPAD)
        cbase[tid] = (tid < nnz) ? (b * LL + g_cols[i][tid]) * (HH * EE) : 0;
    __syncthreads();

    // q fragment in registers (lanes 0-15 and 16-31 read the same 256B row)
    const float4 qv = *(const float4*)(q + ((size_t)(b * LL + i) * HH + h) * EE + el);

    // ---- Phase A: scores. One LDG.128 covers two K rows per iteration. ----
    const float* khl = k + h * EE + el;
    #pragma unroll
    for (int jp = 0; jp < NPAIR; jp++) {
        const int j = 2 * jp + half;
        const float4 kv = *(const float4*)(khl + cbase[j]);
        float d = fmaf(kv.x, qv.x, fmaf(kv.y, qv.y, fmaf(kv.z, qv.z, kv.w * qv.w)));
        d += __shfl_xor_sync(0xFFFFFFFFu, d, 8);
        d += __shfl_xor_sync(0xFFFFFFFFu, d, 4);
        d += __shfl_xor_sync(0xFFFFFFFFu, d, 2);
        d += __shfl_xor_sync(0xFFFFFFFFu, d, 1);
        if ((lane & 15) == 0) ssc[h][j] = d * 0.125f;   // 1/sqrt(64)
    }
    __syncwarp();

    // ---- softmax over nnz entries (lane -> cols {lane, lane+32}) ----
    const int j0 = lane, j1 = lane + 32;
    float s0 = (j0 < nnz) ? ssc[h][j0] : -INFINITY;
    float s1 = (j1 < nnz) ? ssc[h][j1] : -INFINITY;   // only lanes 0..13 hit
    float m = fmaxf(s0, s1);
    #pragma unroll
    for (int o = 16; o > 0; o >>= 1) m = fmaxf(m, __shfl_xor_sync(0xFFFFFFFFu, m, o));
    float e0 = (j0 < nnz) ? __expf(s0 - m) : 0.f;
    float e1 = (j1 < nnz) ? __expf(s1 - m) : 0.f;
    float sum = e0 + e1;
    #pragma unroll
    for (int o = 16; o > 0; o >>= 1) sum += __shfl_xor_sync(0xFFFFFFFFu, sum, o);
    const float inv = 1.f / sum;
    ps[h][j0] = (j0 < nnz) ? e0 * inv : 0.f;            // pads [nnz,32) with 0
    if (lane < 16) ps[h][j1] = (j1 < nnz) ? e1 * inv : 0.f;  // pads up to 47
    __syncwarp();

    // ---- Phase B: weighted V sum, two columns per iteration ----
    const float* vhl = v + h * DD + el;
    float ax = 0.f, ay = 0.f, az = 0.f, aw = 0.f;
    #pragma unroll
    for (int jp = 0; jp < NPAIR; jp++) {
        const int j = 2 * jp + half;
        const float pj = ps[h][j];                       // 0 for padded cols
        const float4 vv = *(const float4*)(vhl + cbase[j]);
        ax = fmaf(pj, vv.x, ax);
        ay = fmaf(pj, vv.y, ay);
        az = fmaf(pj, vv.z, az);
        aw = fmaf(pj, vv.w, aw);
    }
    // combine even/odd column partials across the two 16-lane halves
    ax += __shfl_xor_sync(0xFFFFFFFFu, ax, 16);
    ay += __shfl_xor_sync(0xFFFFFFFFu, ay, 16);
    az += __shfl_xor_sync(0xFFFFFFFFu, az, 16);
    aw += __shfl_xor_sync(0xFFFFFFFFu, aw, 16);
    if (lane < 16) {
        float4* op = (float4*)(out + ((size_t)(b * LL + i) * HH + h) * DD + el);
        *op = make_float4(ax, ay, az, aw);
    }
}

// ---------------------------------------------------------------------------
extern "C" void kernel_launch(void* const* d_in, const int* in_sizes, int n_in,
                              void* d_out, int out_size) {
    const float* q = (const float*)d_in[0];
    const float* k = (const float*)d_in[1];
    const float* v = (const float*)d_in[2];
    // d_in[3] = mask, unused: reconstructed analytically (deterministic for L).
    float* out = (float*)d_out;

    const int lws = (int)ceil(log2((double)LL) / 2.0);  // = 6 for L=2048

    build_cols_kernel<<<(LL + 255) / 256, 256>>>(lws);

    dim3 grid(LL, BB);
    dim3 block(32, HH);
    attn_kernel<<<grid, block>>>(q, k, v, out);
}

// round 10
// speedup vs baseline: 2.3455x; 1.1660x over previous
#include <cuda_runtime.h>
#include <math.h>

// MaskAttention: B=4, L=2048, H=8, E=D=64.
// Sparse attention on the deterministic LocalLogSymmetryMask:
// each row attends <= 46 columns (local +-5 window + log-spaced 1.5^k offsets).
//
// R9: Phase A reduction tree shrunk. 8 lanes per column x 4 columns per
// iteration: same LDG wavefronts (1 line per row per instr) and same FMA
// count, but only 3 shfl per 4 columns (36 total vs 92). cbase stores BYTE
// offsets to cut address ALU. Phase B keeps 16-lane pairing (4 shfls total).

#define BB 4
#define LL 2048
#define HH 8
#define EE 64
#define DD 64
#define MAXNNZ 64   // storage bound; actual nnz <= 46
#define NPAIR 23    // Phase B: ceil(46/2) column pairs
#define NQUAD 12    // Phase A: ceil(48/4) column quads
#define CPAD 48     // padded column-list length

// Scratch: per-row allowed-column lists (rebuilt every launch; deterministic).
__device__ int g_cols[LL][MAXNNZ];
__device__ int g_nnz[LL];

// ---------------------------------------------------------------------------
// Kernel 1: analytically rebuild the allowed-column list for each row.
// Exact port of _build_local_log_symmetry_mask (allowed = mask==False).
// int(1.5^k) is exact in double; k=0 and k=1 both give 1, start at k=1.
// ---------------------------------------------------------------------------
__global__ void build_cols_kernel(int lws) {
    int i = blockIdx.x * blockDim.x + threadIdx.x;
    if (i >= LL) return;

    int cnt = 0;
    int wlo = i - lws + 1;
    int whi = i + lws - 1;

    if (wlo >= 0) {
        double off = 1.5;  // k = 1
        #pragma unroll 1
        for (int k = 1; k < 200; k++) {
            int ni = wlo - (int)off;
            if (ni < 0) break;
            if (cnt < MAXNNZ) g_cols[i][cnt++] = ni;
            off *= 1.5;
        }
    }
    int lo = wlo < 0 ? 0 : wlo;
    int hi = whi >= LL ? LL - 1 : whi;
    for (int j = lo; j <= hi; j++)
        if (cnt < MAXNNZ) g_cols[i][cnt++] = j;
    if (whi < LL) {
        double off = 1.5;  // k = 1
        #pragma unroll 1
        for (int k = 1; k < 200; k++) {
            int ni = whi + (int)off;
            if (ni >= LL) break;
            if (cnt < MAXNNZ) g_cols[i][cnt++] = ni;
            off *= 1.5;
        }
    }
    g_nnz[i] = cnt;
}

// ---------------------------------------------------------------------------
// Kernel 2: sparse attention. Grid (L, B); block (32, 8) = 1 warp per head.
// Phase A: 8 lanes per column, 4 columns per iteration. Lane sl in group g
//   loads K row bytes [sl*16,+16) and [128+sl*16,+16): each LDG.128 touches
//   exactly one 128B line per row -> 8 wavefronts per 4 columns (optimal).
//   Reduce across 8 lanes with 3 shfl; group leader stores the score.
// Softmax via warp shfl. Phase B: 16 lanes per column, 2 cols per iteration,
//   final shfl-xor-16 combine (4 shfls).
// ---------------------------------------------------------------------------
__global__ __launch_bounds__(256) void attn_kernel(
    const float* __restrict__ q,
    const float* __restrict__ k,
    const float* __restrict__ v,
    float* __restrict__ out)
{
    const int i = blockIdx.x;      // query row
    const int b = blockIdx.y;      // batch
    const int h = threadIdx.y;     // head (warp id)
    const int lane = threadIdx.x;
    const int tid = h * 32 + lane;

    __shared__ float ssc[HH][CPAD];     // raw scores
    __shared__ float ps[HH][CPAD];      // probabilities (0-padded)
    __shared__ int   cbase[CPAD];       // (b*LL+col)*H*E*4 BYTE base, 0-padded

    const int nnz = g_nnz[i];
    if (tid < CPAD)
        cbase[tid] = (tid < nnz) ? (b * LL + g_cols[i][tid]) * (HH * EE * 4) : 0;
    __syncthreads();

    // ---- Phase A: scores, 4 columns per iteration ----
    const int g  = lane >> 3;           // column group 0..3
    const int sl = lane & 7;            // sub-lane within group
    const int ea = sl * 4;              // fragment A: elements [ea, ea+4)
    const float* qrow = q + ((size_t)(b * LL + i) * HH + h) * EE;
    const float4 qa = *(const float4*)(qrow + ea);
    const float4 qb = *(const float4*)(qrow + 32 + ea);

    const char* kha = (const char*)(k + h * EE + ea);
    const char* khb = (const char*)(k + h * EE + 32 + ea);

    #pragma unroll
    for (int it = 0; it < NQUAD; it++) {
        const int j = 4 * it + g;
        const int off = cbase[j];
        const float4 kva = *(const float4*)(kha + off);
        const float4 kvb = *(const float4*)(khb + off);
        float d = fmaf(kva.x, qa.x, fmaf(kva.y, qa.y,
                  fmaf(kva.z, qa.z, fmaf(kva.w, qa.w,
                  fmaf(kvb.x, qb.x, fmaf(kvb.y, qb.y,
                  fmaf(kvb.z, qb.z, kvb.w * qb.w)))))));
        d += __shfl_xor_sync(0xFFFFFFFFu, d, 4);
        d += __shfl_xor_sync(0xFFFFFFFFu, d, 2);
        d += __shfl_xor_sync(0xFFFFFFFFu, d, 1);
        if (sl == 0) ssc[h][j] = d * 0.125f;   // 1/sqrt(64)
    }
    __syncwarp();

    // ---- softmax over nnz entries (lane -> cols {lane, lane+32}) ----
    const int j0 = lane, j1 = lane + 32;
    float s0 = (j0 < nnz) ? ssc[h][j0] : -INFINITY;
    float s1 = (j1 < nnz) ? ssc[h][j1] : -INFINITY;   // only lanes 0..13 hit
    float m = fmaxf(s0, s1);
    #pragma unroll
    for (int o = 16; o > 0; o >>= 1) m = fmaxf(m, __shfl_xor_sync(0xFFFFFFFFu, m, o));
    float e0 = (j0 < nnz) ? __expf(s0 - m) : 0.f;
    float e1 = (j1 < nnz) ? __expf(s1 - m) : 0.f;
    float sum = e0 + e1;
    #pragma unroll
    for (int o = 16; o > 0; o >>= 1) sum += __shfl_xor_sync(0xFFFFFFFFu, sum, o);
    const float inv = 1.f / sum;
    ps[h][j0] = (j0 < nnz) ? e0 * inv : 0.f;                  // pads [nnz,32)
    if (lane < 16) ps[h][j1] = (j1 < nnz) ? e1 * inv : 0.f;   // pads up to 47
    __syncwarp();

    // ---- Phase B: weighted V sum, two columns per iteration ----
    const int half = lane >> 4;          // which column of the pair
    const int el = (lane & 15) * 4;      // this lane's d fragment offset
    const char* vhl = (const char*)(v + h * DD + el);
    float ax = 0.f, ay = 0.f, az = 0.f, aw = 0.f;
    #pragma unroll
    for (int jp = 0; jp < NPAIR; jp++) {
        const int j = 2 * jp + half;
        const float pj = ps[h][j];                       // 0 for padded cols
        const float4 vv = *(const float4*)(vhl + cbase[j]);
        ax = fmaf(pj, vv.x, ax);
        ay = fmaf(pj, vv.y, ay);
        az = fmaf(pj, vv.z, az);
        aw = fmaf(pj, vv.w, aw);
    }
    // combine even/odd column partials across the two 16-lane halves
    ax += __shfl_xor_sync(0xFFFFFFFFu, ax, 16);
    ay += __shfl_xor_sync(0xFFFFFFFFu, ay, 16);
    az += __shfl_xor_sync(0xFFFFFFFFu, az, 16);
    aw += __shfl_xor_sync(0xFFFFFFFFu, aw, 16);
    if (lane < 16) {
        float4* op = (float4*)(out + ((size_t)(b * LL + i) * HH + h) * DD + el);
        *op = make_float4(ax, ay, az, aw);
    }
}

// ---------------------------------------------------------------------------
extern "C" void kernel_launch(void* const* d_in, const int* in_sizes, int n_in,
                              void* d_out, int out_size) {
    const float* q = (const float*)d_in[0];
    const float* k = (const float*)d_in[1];
    const float* v = (const float*)d_in[2];
    // d_in[3] = mask, unused: reconstructed analytically (deterministic for L).
    float* out = (float*)d_out;

    const int lws = (int)ceil(log2((double)LL) / 2.0);  // = 6 for L=2048

    build_cols_kernel<<<(LL + 255) / 256, 256>>>(lws);

    dim3 grid(LL, BB);
    dim3 block(32, HH);
    attn_kernel<<<grid, block>>>(q, k, v, out);
}